// round 1
// baseline (speedup 1.0000x reference)
#include <cuda_runtime.h>
#include <math.h>

// ---------------- problem constants ----------------
#define Bc      4
#define Lc      2048
#define DIMc    1024
#define DINNER  2048      // EXPAND * DIM
#define DSTATE  16
#define DCONV   4
#define DTRANK  64        // ceil(1024/16)
#define MROWS   (Bc*Lc)   // 8192 tokens
#define XDBL_N  (DTRANK + 2*DSTATE)  // 96

// ---------------- scratch (device globals; no allocs allowed) ----------------
__device__ float g_xn  [(size_t)MROWS * DIMc];        // 32 MB
__device__ float g_xz  [(size_t)MROWS * 2 * DINNER];  // 128 MB
__device__ float g_uc  [(size_t)MROWS * DINNER];      // 64 MB
__device__ float g_xdbl[(size_t)MROWS * XDBL_N];      // 3 MB
__device__ float g_dt  [(size_t)MROWS * DINNER];      // 64 MB
__device__ float g_y   [(size_t)MROWS * DINNER];      // 64 MB

// ---------------- LayerNorm ----------------
__global__ __launch_bounds__(256) void ln_kernel(const float* __restrict__ x,
                                                 const float* __restrict__ g,
                                                 const float* __restrict__ b) {
    int row = blockIdx.x;
    const float* xr = x + (size_t)row * DIMc;
    float sum = 0.f, sq = 0.f;
    for (int i = threadIdx.x; i < DIMc; i += 256) {
        float v = xr[i];
        sum += v; sq += v * v;
    }
    #pragma unroll
    for (int o = 16; o; o >>= 1) {
        sum += __shfl_xor_sync(0xffffffffu, sum, o);
        sq  += __shfl_xor_sync(0xffffffffu, sq, o);
    }
    __shared__ float s1[8], s2[8], red[2];
    int w = threadIdx.x >> 5, l = threadIdx.x & 31;
    if (l == 0) { s1[w] = sum; s2[w] = sq; }
    __syncthreads();
    if (threadIdx.x == 0) {
        float a = 0.f, c = 0.f;
        #pragma unroll
        for (int i = 0; i < 8; i++) { a += s1[i]; c += s2[i]; }
        float mu = a / DIMc;
        red[0] = mu;
        red[1] = c / DIMc - mu * mu;
    }
    __syncthreads();
    float mu = red[0];
    float inv = rsqrtf(red[1] + 1e-5f);
    float* out = g_xn + (size_t)row * DIMc;
    for (int i = threadIdx.x; i < DIMc; i += 256)
        out[i] = (xr[i] - mu) * inv * g[i] + b[i];
}

// ---------------- generic TN SGEMM: C[m,n] = f(sum_k A[m,k]*B[n,k] + bias[n]) (+resid) ----------------
// Both A and B are K-contiguous row-major. BM=BN=128, BK=16, 256 threads, 8x8 microtile.
__global__ __launch_bounds__(256) void sgemm_tn(
    const float* __restrict__ A, int lda,
    const float* __restrict__ Bw, int ldb,
    float* __restrict__ C, int ldc,
    int N, int K,
    const float* __restrict__ bias,
    const float* __restrict__ resid, int ldr,
    int act)  // 0=none, 1=softplus
{
    __shared__ float As[16][128 + 4];
    __shared__ float Bs[16][128 + 4];
    int bm = blockIdx.y * 128;
    int bn = blockIdx.x * 128;
    int tid = threadIdx.x;
    int tx = tid & 15, ty = tid >> 4;

    float acc[8][8];
    #pragma unroll
    for (int i = 0; i < 8; i++)
        #pragma unroll
        for (int j = 0; j < 8; j++) acc[i][j] = 0.f;

    const float* Aptr = A + (size_t)bm * lda;
    const float* Bptr = Bw + (size_t)bn * ldb;

    for (int k0 = 0; k0 < K; k0 += 16) {
        #pragma unroll
        for (int it = 0; it < 2; it++) {
            int i  = tid + it * 256;
            int r  = i >> 2;          // 0..127
            int kc = (i & 3) * 4;     // 0,4,8,12
            float4 va = *(const float4*)(Aptr + (size_t)r * lda + k0 + kc);
            As[kc + 0][r] = va.x; As[kc + 1][r] = va.y;
            As[kc + 2][r] = va.z; As[kc + 3][r] = va.w;
            float4 vb;
            if (bn + r < N) vb = *(const float4*)(Bptr + (size_t)r * ldb + k0 + kc);
            else            vb = make_float4(0.f, 0.f, 0.f, 0.f);
            Bs[kc + 0][r] = vb.x; Bs[kc + 1][r] = vb.y;
            Bs[kc + 2][r] = vb.z; Bs[kc + 3][r] = vb.w;
        }
        __syncthreads();
        #pragma unroll
        for (int k = 0; k < 16; k++) {
            float a[8], bfr[8];
            #pragma unroll
            for (int i = 0; i < 8; i++) a[i]   = As[k][ty * 8 + i];
            #pragma unroll
            for (int j = 0; j < 8; j++) bfr[j] = Bs[k][tx * 8 + j];
            #pragma unroll
            for (int i = 0; i < 8; i++)
                #pragma unroll
                for (int j = 0; j < 8; j++)
                    acc[i][j] = fmaf(a[i], bfr[j], acc[i][j]);
        }
        __syncthreads();
    }

    #pragma unroll
    for (int i = 0; i < 8; i++) {
        int m = bm + ty * 8 + i;
        #pragma unroll
        for (int j = 0; j < 8; j++) {
            int n = bn + tx * 8 + j;
            if (n < N) {
                float v = acc[i][j];
                if (bias)     v += bias[n];
                if (act == 1) v = (v > 20.f) ? v : log1pf(expf(v));
                if (resid)    v += resid[(size_t)m * ldr + n];
                C[(size_t)m * ldc + n] = v;
            }
        }
    }
}

// ---------------- depthwise causal conv (k=4) + SiLU ----------------
__global__ __launch_bounds__(256) void conv_silu_kernel(const float* __restrict__ convw,
                                                        const float* __restrict__ convb) {
    int idx = blockIdx.x * 256 + threadIdx.x;   // over MROWS*DINNER
    if (idx >= MROWS * DINNER) return;
    int d = idx & (DINNER - 1);
    int m = idx >> 11;                           // token index
    int l = m & (Lc - 1);
    float acc = convb[d];
    #pragma unroll
    for (int k = 0; k < DCONV; k++) {
        int ll = l - (DCONV - 1) + k;
        if (ll >= 0)
            acc = fmaf(g_xz[(size_t)(m - (DCONV - 1) + k) * (2 * DINNER) + d],
                       convw[d * DCONV + k], acc);
    }
    acc = acc / (1.f + expf(-acc));              // SiLU
    g_uc[idx] = acc;
}

// ---------------- selective scan: one thread per (b, d, n) state ----------------
__global__ __launch_bounds__(256) void scan_kernel(const float* __restrict__ A_log,
                                                   const float* __restrict__ Dp) {
    int t = blockIdx.x * 256 + threadIdx.x;      // 0 .. B*DINNER*16-1
    int n = t & 15;
    int d = (t >> 4) & (DINNER - 1);
    int b = t >> 15;
    float A  = -expf(A_log[d * DSTATE + n]);
    float Dd = Dp[d];
    float h  = 0.f;
    size_t base = (size_t)b * Lc;
    for (int l = 0; l < Lc; l++) {
        size_t m  = base + l;
        float dt = g_dt[m * DINNER + d];
        float u  = g_uc[m * DINNER + d];
        float Bn = g_xdbl[m * XDBL_N + DTRANK + n];
        float Cn = g_xdbl[m * XDBL_N + DTRANK + DSTATE + n];
        float dA = expf(dt * A);
        h = fmaf(dA, h, dt * u * Bn);
        float p = h * Cn;
        p += __shfl_xor_sync(0xffffffffu, p, 8);
        p += __shfl_xor_sync(0xffffffffu, p, 4);
        p += __shfl_xor_sync(0xffffffffu, p, 2);
        p += __shfl_xor_sync(0xffffffffu, p, 1);
        if (n == 0) {
            float z = g_xz[m * (2 * DINNER) + DINNER + d];
            float y = (p + u * Dd) * (z / (1.f + expf(-z)));
            g_y[m * DINNER + d] = y;
        }
    }
}

// ---------------- launch ----------------
extern "C" void kernel_launch(void* const* d_in, const int* in_sizes, int n_in,
                              void* d_out, int out_size) {
    const float* x      = (const float*)d_in[0];
    const float* ln_g   = (const float*)d_in[1];
    const float* ln_b   = (const float*)d_in[2];
    const float* W_in   = (const float*)d_in[3];
    const float* conv_w = (const float*)d_in[4];
    const float* conv_b = (const float*)d_in[5];
    const float* W_x    = (const float*)d_in[6];
    const float* W_dt   = (const float*)d_in[7];
    const float* b_dt   = (const float*)d_in[8];
    const float* A_log  = (const float*)d_in[9];
    const float* Dvec   = (const float*)d_in[10];
    const float* W_out  = (const float*)d_in[11];
    float* out = (float*)d_out;

    float *xn, *xz, *uc, *xdbl, *dt, *y;
    cudaGetSymbolAddress((void**)&xn,   g_xn);
    cudaGetSymbolAddress((void**)&xz,   g_xz);
    cudaGetSymbolAddress((void**)&uc,   g_uc);
    cudaGetSymbolAddress((void**)&xdbl, g_xdbl);
    cudaGetSymbolAddress((void**)&dt,   g_dt);
    cudaGetSymbolAddress((void**)&y,    g_y);

    // 1. LayerNorm
    ln_kernel<<<MROWS, 256>>>(x, ln_g, ln_b);

    // 2. xz = xn @ W_in^T   (8192 x 4096 x 1024)
    sgemm_tn<<<dim3(4096 / 128, MROWS / 128), 256>>>(
        xn, DIMc, W_in, DIMc, xz, 2 * DINNER, 2 * DINNER, DIMc,
        nullptr, nullptr, 0, 0);

    // 3. depthwise conv + SiLU on u = xz[:, :DINNER]
    conv_silu_kernel<<<(MROWS * DINNER) / 256, 256>>>(conv_w, conv_b);

    // 4. x_dbl = uc @ W_x^T  (8192 x 96 x 2048)
    sgemm_tn<<<dim3(1, MROWS / 128), 256>>>(
        uc, DINNER, W_x, DINNER, xdbl, XDBL_N, XDBL_N, DINNER,
        nullptr, nullptr, 0, 0);

    // 5. dt = softplus(dt_r @ W_dt^T + b_dt)  (8192 x 2048 x 64)
    sgemm_tn<<<dim3(DINNER / 128, MROWS / 128), 256>>>(
        xdbl, XDBL_N, W_dt, DTRANK, dt, DINNER, DINNER, DTRANK,
        b_dt, nullptr, 0, 1);

    // 6. selective scan + D skip + SiLU(z) gating
    scan_kernel<<<(Bc * DINNER * DSTATE) / 256, 256>>>(A_log, Dvec);

    // 7. out = x + y @ W_out^T  (8192 x 1024 x 2048)
    sgemm_tn<<<dim3(DIMc / 128, MROWS / 128), 256>>>(
        y, DINNER, W_out, DINNER, out, DIMc, DIMc, DINNER,
        nullptr, x, DIMc, 0);
}

// round 3
// speedup vs baseline: 1.6695x; 1.6695x over previous
#include <cuda_runtime.h>
#include <cuda_bf16.h>
#include <math.h>
#include <stdint.h>

// ---------------- problem constants ----------------
#define Bc      4
#define Lc      2048
#define DIMc    1024
#define DINNER  2048
#define DSTATE  16
#define DCONV   4
#define DTRANK  64
#define MROWS   (Bc*Lc)        // 8192
#define XDBL_N  96

// ---------------- scratch (device globals) ----------------
__device__ __nv_bfloat16 g_xnE  [(size_t)MROWS * 2 * DIMc];    // [8192, 2048]  A of GEMM1 (hi|lo)
__device__ __nv_bfloat16 g_WinE [(size_t)4096 * 2 * DIMc];     // [4096, 2048]  B of GEMM1
__device__ float         g_xz   [(size_t)MROWS * 2 * DINNER];  // GEMM1 out (u|z) fp32
__device__ float         g_ucF  [(size_t)MROWS * DINNER];      // conv+silu out fp32 (scan)
__device__ __nv_bfloat16 g_ucE  [(size_t)MROWS * 2 * DINNER];  // [8192, 4096]  A of GEMM2
__device__ __nv_bfloat16 g_WxE  [(size_t)128 * 2 * DINNER];    // [128, 4096]   B of GEMM2 (N pad 96->128)
__device__ float         g_xdbl [(size_t)MROWS * XDBL_N];      // GEMM2 out fp32
__device__ __nv_bfloat16 g_dtrE [(size_t)MROWS * 2 * DTRANK];  // [8192, 128]   A of GEMM3
__device__ __nv_bfloat16 g_WdtE [(size_t)DINNER * 2 * DTRANK]; // [2048, 128]   B of GEMM3
__device__ float         g_dt   [(size_t)MROWS * DINNER];      // GEMM3 out fp32
__device__ __nv_bfloat16 g_yE   [(size_t)MROWS * 2 * DINNER];  // [8192, 4096]  A of GEMM4
__device__ __nv_bfloat16 g_WoutE[(size_t)DIMc * 2 * DINNER];   // [1024, 4096]  B of GEMM4

// ---------------- helpers ----------------
__device__ __forceinline__ uint32_t smem_u32(const void* p) {
    uint32_t a;
    asm("{ .reg .u64 t; cvta.to.shared.u64 t, %1; cvt.u32.u64 %0, t; }" : "=r"(a) : "l"(p));
    return a;
}
__device__ __forceinline__ void split_bf16(float v, __nv_bfloat16& h, __nv_bfloat16& l) {
    h = __float2bfloat16(v);
    l = __float2bfloat16(v - __bfloat162float(h));
}
#define CP16(dst, src) asm volatile("cp.async.cg.shared.global [%0], [%1], 16;" \
    :: "r"(dst), "l"(src) : "memory")
#define CP_COMMIT()    asm volatile("cp.async.commit_group;" ::: "memory")
#define CP_WAIT(n)     asm volatile("cp.async.wait_group %0;" :: "n"(n) : "memory")

// ---------------- warp-MMA split-bf16 GEMM ----------------
// C[m,n] = sum_k Afp32[m,k]*Bfp32[n,k] via extended bf16 operands A=[hi|lo],
// B=[hi|lo] (row-major, 2*Kh cols). Terms: Ah*Bh + Ah*Bl + Al*Bh.
// BM=128, BN=64, BK=64; 256 threads; 2-stage cp.async pipeline.
#define STAGE_BYTES 24576   // A: 128*128B = 16384, B: 64*128B = 8192

__global__ __launch_bounds__(256)
void gemm_mma(const __nv_bfloat16* __restrict__ A,
              const __nv_bfloat16* __restrict__ Bw,
              float* __restrict__ C, int ldc, int Nact, int Kh,
              const float* __restrict__ bias,
              const float* __restrict__ resid, int ldr, int act) {
    __shared__ __align__(1024) unsigned char sm[2 * STAGE_BYTES];
    uint32_t sbase = smem_u32(sm);
    int tid = threadIdx.x, lane = tid & 31, wid = tid >> 5;
    int bm = blockIdx.y * 128, bn = blockIdx.x * 64;
    int wm = wid >> 1, wn = wid & 1;
    size_t lda = 2 * (size_t)Kh;

    float acc[2][4][4];
    #pragma unroll
    for (int i = 0; i < 2; i++)
        #pragma unroll
        for (int j = 0; j < 4; j++)
            #pragma unroll
            for (int q = 0; q < 4; q++) acc[i][j][q] = 0.f;

    const int ncc = Kh >> 6;
    const int nch = 3 * ncc;

    auto issue_load = [&](int stage, int c) {
        int term = (c >= ncc) + (c >= 2 * ncc);
        int cc   = c - term * ncc;
        int aoff = ((term == 2) ? Kh : 0) + cc * 64;
        int boff = ((term == 1) ? Kh : 0) + cc * 64;
        uint32_t sA = sbase + stage * STAGE_BYTES;
        uint32_t sB = sA + 16384;
        #pragma unroll
        for (int it = 0; it < 4; it++) {
            int idx = tid + it * 256;
            int r = idx >> 3, u = idx & 7;
            uint32_t dst = sA + r * 128 + ((u ^ (r & 7)) << 4);
            size_t gsrc = __cvta_generic_to_global(A + (size_t)(bm + r) * lda + aoff + u * 8);
            CP16(dst, gsrc);
        }
        #pragma unroll
        for (int it = 0; it < 2; it++) {
            int idx = tid + it * 256;
            int r = idx >> 3, u = idx & 7;
            uint32_t dst = sB + r * 128 + ((u ^ (r & 7)) << 4);
            size_t gsrc = __cvta_generic_to_global(Bw + (size_t)(bn + r) * lda + boff + u * 8);
            CP16(dst, gsrc);
        }
        CP_COMMIT();
    };

    issue_load(0, 0);
    for (int c = 0; c < nch; c++) {
        int stage = c & 1;
        if (c + 1 < nch) issue_load(stage ^ 1, c + 1);
        if (c + 1 < nch) CP_WAIT(1); else CP_WAIT(0);
        __syncthreads();

        uint32_t sA = sbase + stage * STAGE_BYTES;
        uint32_t sB = sA + 16384;
        #pragma unroll
        for (int ks = 0; ks < 4; ks++) {
            uint32_t a[2][4], b[4][2];
            #pragma unroll
            for (int i = 0; i < 2; i++) {
                int r = wm * 32 + i * 16 + (lane & 15);
                int u = ks * 2 + (lane >> 4);
                uint32_t addr = sA + r * 128 + ((u ^ (r & 7)) << 4);
                asm volatile("ldmatrix.sync.aligned.m8n8.x4.shared.b16 {%0,%1,%2,%3}, [%4];"
                    : "=r"(a[i][0]), "=r"(a[i][1]), "=r"(a[i][2]), "=r"(a[i][3]) : "r"(addr));
            }
            #pragma unroll
            for (int jj = 0; jj < 2; jj++) {
                int r = wn * 32 + jj * 16 + ((lane >> 4) << 3) + (lane & 7);
                int u = ks * 2 + ((lane >> 3) & 1);
                uint32_t addr = sB + r * 128 + ((u ^ (r & 7)) << 4);
                asm volatile("ldmatrix.sync.aligned.m8n8.x4.shared.b16 {%0,%1,%2,%3}, [%4];"
                    : "=r"(b[jj*2][0]), "=r"(b[jj*2][1]), "=r"(b[jj*2+1][0]), "=r"(b[jj*2+1][1])
                    : "r"(addr));
            }
            #pragma unroll
            for (int i = 0; i < 2; i++)
                #pragma unroll
                for (int j = 0; j < 4; j++)
                    asm volatile(
                        "mma.sync.aligned.m16n8k16.row.col.f32.bf16.bf16.f32 "
                        "{%0,%1,%2,%3}, {%4,%5,%6,%7}, {%8,%9}, {%0,%1,%2,%3};"
                        : "+f"(acc[i][j][0]), "+f"(acc[i][j][1]),
                          "+f"(acc[i][j][2]), "+f"(acc[i][j][3])
                        : "r"(a[i][0]), "r"(a[i][1]), "r"(a[i][2]), "r"(a[i][3]),
                          "r"(b[j][0]), "r"(b[j][1]));
        }
        __syncthreads();
    }

    // ---- epilogue: direct stores with fused bias / softplus / residual ----
    #pragma unroll
    for (int i = 0; i < 2; i++) {
        int r0 = bm + wm * 32 + i * 16 + (lane >> 2);
        #pragma unroll
        for (int j = 0; j < 4; j++) {
            int n0 = bn + wn * 32 + j * 8 + 2 * (lane & 3);
            #pragma unroll
            for (int h = 0; h < 2; h++) {
                int r = r0 + h * 8;
                float v0 = acc[i][j][h * 2 + 0];
                float v1 = acc[i][j][h * 2 + 1];
                if (bias) { v0 += bias[n0]; v1 += bias[n0 + 1]; }
                if (act) {
                    v0 = (v0 > 20.f) ? v0 : log1pf(expf(v0));
                    v1 = (v1 > 20.f) ? v1 : log1pf(expf(v1));
                }
                if (resid) {
                    v0 += resid[(size_t)r * ldr + n0];
                    v1 += resid[(size_t)r * ldr + n0 + 1];
                }
                if (n0 + 1 < Nact) {
                    *(float2*)(C + (size_t)r * ldc + n0) = make_float2(v0, v1);
                } else if (n0 < Nact) {
                    C[(size_t)r * ldc + n0] = v0;
                }
            }
        }
    }
}

// ---------------- LayerNorm -> split-bf16 extended A ----------------
__global__ __launch_bounds__(256) void ln_kernel(const float* __restrict__ x,
                                                 const float* __restrict__ g,
                                                 const float* __restrict__ b) {
    int row = blockIdx.x;
    const float* xr = x + (size_t)row * DIMc;
    float sum = 0.f, sq = 0.f;
    for (int i = threadIdx.x; i < DIMc; i += 256) {
        float v = xr[i];
        sum += v; sq += v * v;
    }
    #pragma unroll
    for (int o = 16; o; o >>= 1) {
        sum += __shfl_xor_sync(0xffffffffu, sum, o);
        sq  += __shfl_xor_sync(0xffffffffu, sq, o);
    }
    __shared__ float s1[8], s2[8], red[2];
    int w = threadIdx.x >> 5, l = threadIdx.x & 31;
    if (l == 0) { s1[w] = sum; s2[w] = sq; }
    __syncthreads();
    if (threadIdx.x == 0) {
        float a = 0.f, c = 0.f;
        #pragma unroll
        for (int i = 0; i < 8; i++) { a += s1[i]; c += s2[i]; }
        float mu = a / DIMc;
        red[0] = mu;
        red[1] = c / DIMc - mu * mu;
    }
    __syncthreads();
    float mu = red[0];
    float inv = rsqrtf(red[1] + 1e-5f);
    __nv_bfloat16* out = g_xnE + (size_t)row * 2 * DIMc;
    for (int i = threadIdx.x; i < DIMc; i += 256) {
        float v = (xr[i] - mu) * inv * g[i] + b[i];
        __nv_bfloat16 h, lo;
        split_bf16(v, h, lo);
        out[i] = h;
        out[DIMc + i] = lo;
    }
}

// ---------------- weight -> split-bf16 ext (with row padding) ----------------
__global__ __launch_bounds__(256) void wext_kernel(const float* __restrict__ W,
                                                   __nv_bfloat16* __restrict__ out,
                                                   int Rin, int K, int total) {
    int idx = blockIdx.x * 256 + threadIdx.x;
    if (idx >= total) return;
    int r = idx / K, k = idx - r * K;
    float v = (r < Rin) ? W[(size_t)r * K + k] : 0.f;
    __nv_bfloat16 h, lo;
    split_bf16(v, h, lo);
    out[(size_t)r * 2 * K + k]     = h;
    out[(size_t)r * 2 * K + K + k] = lo;
}

// ---------------- depthwise causal conv (k=4) + SiLU ----------------
__global__ __launch_bounds__(256) void conv_silu_kernel(const float* __restrict__ convw,
                                                        const float* __restrict__ convb) {
    int idx = blockIdx.x * 256 + threadIdx.x;
    if (idx >= MROWS * DINNER) return;
    int d = idx & (DINNER - 1);
    int m = idx >> 11;
    int l = m & (Lc - 1);
    float acc = convb[d];
    #pragma unroll
    for (int k = 0; k < DCONV; k++) {
        int ll = l - (DCONV - 1) + k;
        if (ll >= 0)
            acc = fmaf(g_xz[(size_t)(m - (DCONV - 1) + k) * (2 * DINNER) + d],
                       convw[d * DCONV + k], acc);
    }
    acc = acc / (1.f + expf(-acc));
    g_ucF[idx] = acc;
    __nv_bfloat16 h, lo;
    split_bf16(acc, h, lo);
    g_ucE[(size_t)m * 2 * DINNER + d]          = h;
    g_ucE[(size_t)m * 2 * DINNER + DINNER + d] = lo;
}

// ---------------- dt_r slice -> split-bf16 ext ----------------
__global__ __launch_bounds__(256) void dtr_kernel() {
    int idx = blockIdx.x * 256 + threadIdx.x;
    if (idx >= MROWS * DTRANK) return;
    int m = idx >> 6, k = idx & 63;
    float v = g_xdbl[(size_t)m * XDBL_N + k];
    __nv_bfloat16 h, lo;
    split_bf16(v, h, lo);
    g_dtrE[(size_t)m * 2 * DTRANK + k]          = h;
    g_dtrE[(size_t)m * 2 * DTRANK + DTRANK + k] = lo;
}

// ---------------- selective scan + gate -> split-bf16 y ----------------
__global__ __launch_bounds__(256) void scan_kernel(const float* __restrict__ A_log,
                                                   const float* __restrict__ Dp) {
    int t = blockIdx.x * 256 + threadIdx.x;
    int n = t & 15;
    int d = (t >> 4) & (DINNER - 1);
    int b = t >> 15;
    float A  = -expf(A_log[d * DSTATE + n]);
    float Dd = Dp[d];
    float h  = 0.f;
    size_t base = (size_t)b * Lc;
    for (int l = 0; l < Lc; l++) {
        size_t m = base + l;
        float dt = g_dt[m * DINNER + d];
        float u  = g_ucF[m * DINNER + d];
        float Bn = g_xdbl[m * XDBL_N + DTRANK + n];
        float Cn = g_xdbl[m * XDBL_N + DTRANK + DSTATE + n];
        float dA = expf(dt * A);
        h = fmaf(dA, h, dt * u * Bn);
        float p = h * Cn;
        p += __shfl_xor_sync(0xffffffffu, p, 8);
        p += __shfl_xor_sync(0xffffffffu, p, 4);
        p += __shfl_xor_sync(0xffffffffu, p, 2);
        p += __shfl_xor_sync(0xffffffffu, p, 1);
        if (n == 0) {
            float z = g_xz[m * (2 * DINNER) + DINNER + d];
            float y = (p + u * Dd) * (z / (1.f + expf(-z)));
            __nv_bfloat16 hh, lo;
            split_bf16(y, hh, lo);
            g_yE[m * 2 * DINNER + d]          = hh;
            g_yE[m * 2 * DINNER + DINNER + d] = lo;
        }
    }
}

// ---------------- launch ----------------
extern "C" void kernel_launch(void* const* d_in, const int* in_sizes, int n_in,
                              void* d_out, int out_size) {
    const float* x      = (const float*)d_in[0];
    const float* ln_g   = (const float*)d_in[1];
    const float* ln_b   = (const float*)d_in[2];
    const float* W_in   = (const float*)d_in[3];
    const float* conv_w = (const float*)d_in[4];
    const float* conv_b = (const float*)d_in[5];
    const float* W_x    = (const float*)d_in[6];
    const float* W_dt   = (const float*)d_in[7];
    const float* b_dt   = (const float*)d_in[8];
    const float* A_log  = (const float*)d_in[9];
    const float* Dvec   = (const float*)d_in[10];
    const float* W_out  = (const float*)d_in[11];
    float* out = (float*)d_out;

    __nv_bfloat16 *xnE, *WinE, *ucE, *WxE, *dtrE, *WdtE, *yE, *WoutE;
    float *xz, *xdbl, *dt;
    cudaGetSymbolAddress((void**)&xnE,   g_xnE);
    cudaGetSymbolAddress((void**)&WinE,  g_WinE);
    cudaGetSymbolAddress((void**)&xz,    g_xz);
    cudaGetSymbolAddress((void**)&ucE,   g_ucE);
    cudaGetSymbolAddress((void**)&WxE,   g_WxE);
    cudaGetSymbolAddress((void**)&xdbl,  g_xdbl);
    cudaGetSymbolAddress((void**)&dtrE,  g_dtrE);
    cudaGetSymbolAddress((void**)&WdtE,  g_WdtE);
    cudaGetSymbolAddress((void**)&dt,    g_dt);
    cudaGetSymbolAddress((void**)&yE,    g_yE);
    cudaGetSymbolAddress((void**)&WoutE, g_WoutE);

    // weight conversions + LN
    wext_kernel<<<(4096 * DIMc + 255) / 256, 256>>>(W_in, WinE, 4096, DIMc, 4096 * DIMc);
    wext_kernel<<<(128 * DINNER + 255) / 256, 256>>>(W_x, WxE, XDBL_N, DINNER, 128 * DINNER);
    wext_kernel<<<(DINNER * DTRANK + 255) / 256, 256>>>(W_dt, WdtE, DINNER, DTRANK, DINNER * DTRANK);
    wext_kernel<<<(DIMc * DINNER + 255) / 256, 256>>>(W_out, WoutE, DIMc, DINNER, DIMc * DINNER);
    ln_kernel<<<MROWS, 256>>>(x, ln_g, ln_b);

    // GEMM1: xz = xn @ W_in^T   (8192 x 4096, K=1024)
    gemm_mma<<<dim3(4096 / 64, MROWS / 128), 256>>>(
        xnE, WinE, xz, 2 * DINNER, 2 * DINNER, DIMc, nullptr, nullptr, 0, 0);

    // conv + SiLU
    conv_silu_kernel<<<(MROWS * DINNER) / 256, 256>>>(conv_w, conv_b);

    // GEMM2: x_dbl = uc @ W_x^T  (8192 x 96 -> padded 128, K=2048)
    gemm_mma<<<dim3(2, MROWS / 128), 256>>>(
        ucE, WxE, xdbl, XDBL_N, XDBL_N, DINNER, nullptr, nullptr, 0, 0);

    // dt_r extraction
    dtr_kernel<<<(MROWS * DTRANK) / 256, 256>>>();

    // GEMM3: dt = softplus(dt_r @ W_dt^T + b_dt)  (8192 x 2048, K=64)
    gemm_mma<<<dim3(DINNER / 64, MROWS / 128), 256>>>(
        dtrE, WdtE, dt, DINNER, DINNER, DTRANK, b_dt, nullptr, 0, 1);

    // scan + gating -> yE
    scan_kernel<<<(Bc * DINNER * DSTATE) / 256, 256>>>(A_log, Dvec);

    // GEMM4: out = x + y @ W_out^T  (8192 x 1024, K=2048)
    gemm_mma<<<dim3(DIMc / 64, MROWS / 128), 256>>>(
        yE, WoutE, out, DIMc, DIMc, DINNER, nullptr, x, DIMc, 0);
}

// round 4
// speedup vs baseline: 1.6944x; 1.0149x over previous
#include <cuda_runtime.h>
#include <cuda_bf16.h>
#include <math.h>
#include <stdint.h>

// ---------------- problem constants ----------------
#define Bc      4
#define Lc      2048
#define DIMc    1024
#define DINNER  2048
#define DSTATE  16
#define DCONV   4
#define DTRANK  64
#define MROWS   (Bc*Lc)        // 8192
#define XDBL_N  96

// ---------------- scratch (device globals) ----------------
__device__ __nv_bfloat16 g_xnE  [(size_t)MROWS * 2 * DIMc];
__device__ __nv_bfloat16 g_WinE [(size_t)4096 * 2 * DIMc];
__device__ float         g_xz   [(size_t)MROWS * 2 * DINNER];
__device__ float         g_ucF  [(size_t)MROWS * DINNER];
__device__ __nv_bfloat16 g_ucE  [(size_t)MROWS * 2 * DINNER];
__device__ __nv_bfloat16 g_WxE  [(size_t)128 * 2 * DINNER];
__device__ float         g_xdbl [(size_t)MROWS * XDBL_N];
__device__ __nv_bfloat16 g_dtrE [(size_t)MROWS * 2 * DTRANK];
__device__ __nv_bfloat16 g_WdtE [(size_t)DINNER * 2 * DTRANK];
__device__ float         g_dt   [(size_t)MROWS * DINNER];
__device__ __nv_bfloat16 g_yE   [(size_t)MROWS * 2 * DINNER];
__device__ __nv_bfloat16 g_WoutE[(size_t)DIMc * 2 * DINNER];

// ---------------- helpers ----------------
__device__ __forceinline__ uint32_t smem_u32(const void* p) {
    uint32_t a;
    asm("{ .reg .u64 t; cvta.to.shared.u64 t, %1; cvt.u32.u64 %0, t; }" : "=r"(a) : "l"(p));
    return a;
}
__device__ __forceinline__ void split_bf16(float v, __nv_bfloat16& h, __nv_bfloat16& l) {
    h = __float2bfloat16(v);
    l = __float2bfloat16(v - __bfloat162float(h));
}
#define CP16(dst, src) asm volatile("cp.async.cg.shared.global [%0], [%1], 16;" \
    :: "r"(dst), "l"(src) : "memory")
#define CP_COMMIT()    asm volatile("cp.async.commit_group;" ::: "memory")
#define CP_WAIT(n)     asm volatile("cp.async.wait_group %0;" :: "n"(n) : "memory")

// ---------------- warp-MMA split-bf16 GEMM ----------------
// C[m,n] = sum_k Afp32[m,k]*Bfp32[n,k] via extended bf16 operands [hi|lo],
// terms Ah*Bh + Ah*Bl + Al*Bh.  BM x 128 tile, BK=64, 3-stage cp.async.
template<int BM>
__global__ __launch_bounds__(256, 2)
void gemm_mma(const __nv_bfloat16* __restrict__ A,
              const __nv_bfloat16* __restrict__ Bw,
              float* __restrict__ C, int ldc, int Nact, int Kh,
              const float* __restrict__ bias,
              const float* __restrict__ resid, int ldr, int act) {
    constexpr int ABYTES = BM * 128;          // BM rows x 64 bf16
    constexpr int BBYTES = 128 * 128;         // 128 rows x 64 bf16
    constexpr int STG    = ABYTES + BBYTES;
    constexpr int WMC    = BM / 32;           // warps along M
    constexpr int WNC    = 8 / WMC;           // warps along N
    constexpr int WTN    = 128 / WNC;         // warp N tile
    constexpr int BJ     = WTN / 8;           // n8 frags per warp

    extern __shared__ __align__(1024) unsigned char sm[];
    uint32_t sbase = smem_u32(sm);
    int tid = threadIdx.x, lane = tid & 31, wid = tid >> 5;
    int bm = blockIdx.y * BM, bn = blockIdx.x * 128;
    int wm = wid % WMC, wn = wid / WMC;
    size_t lda = 2 * (size_t)Kh;

    float acc[2][BJ][4];
    #pragma unroll
    for (int i = 0; i < 2; i++)
        #pragma unroll
        for (int j = 0; j < BJ; j++)
            #pragma unroll
            for (int q = 0; q < 4; q++) acc[i][j][q] = 0.f;

    const int ncc = Kh >> 6;
    const int nch = 3 * ncc;

    auto issue_load = [&](int stage, int c) {
        int term = (c >= ncc) + (c >= 2 * ncc);
        int cc   = c - term * ncc;
        int aoff = ((term == 2) ? Kh : 0) + cc * 64;
        int boff = ((term == 1) ? Kh : 0) + cc * 64;
        uint32_t sA = sbase + stage * STG;
        uint32_t sB = sA + ABYTES;
        #pragma unroll
        for (int it = 0; it < BM / 32; it++) {
            int idx = tid + it * 256;
            int r = idx >> 3, u = idx & 7;
            uint32_t dst = sA + r * 128 + ((u ^ (r & 7)) << 4);
            size_t gsrc = __cvta_generic_to_global(A + (size_t)(bm + r) * lda + aoff + u * 8);
            CP16(dst, gsrc);
        }
        #pragma unroll
        for (int it = 0; it < 4; it++) {
            int idx = tid + it * 256;
            int r = idx >> 3, u = idx & 7;
            uint32_t dst = sB + r * 128 + ((u ^ (r & 7)) << 4);
            size_t gsrc = __cvta_generic_to_global(Bw + (size_t)(bn + r) * lda + boff + u * 8);
            CP16(dst, gsrc);
        }
        CP_COMMIT();
    };

    issue_load(0, 0);
    if (nch > 1) issue_load(1, 1);

    for (int c = 0; c < nch; c++) {
        int stage = c % 3;
        if (c + 2 < nch) { issue_load((c + 2) % 3, c + 2); CP_WAIT(2); }
        else if (c + 1 < nch) CP_WAIT(1);
        else CP_WAIT(0);
        __syncthreads();

        uint32_t sA = sbase + stage * STG;
        uint32_t sB = sA + ABYTES;
        #pragma unroll
        for (int ks = 0; ks < 4; ks++) {
            uint32_t a[2][4], b[BJ][2];
            #pragma unroll
            for (int i = 0; i < 2; i++) {
                int r = wm * 32 + i * 16 + (lane & 15);
                int u = ks * 2 + (lane >> 4);
                uint32_t addr = sA + r * 128 + ((u ^ (r & 7)) << 4);
                asm volatile("ldmatrix.sync.aligned.m8n8.x4.shared.b16 {%0,%1,%2,%3}, [%4];"
                    : "=r"(a[i][0]), "=r"(a[i][1]), "=r"(a[i][2]), "=r"(a[i][3]) : "r"(addr));
            }
            #pragma unroll
            for (int jj = 0; jj < BJ / 2; jj++) {
                int r = wn * WTN + jj * 16 + ((lane >> 4) << 3) + (lane & 7);
                int u = ks * 2 + ((lane >> 3) & 1);
                uint32_t addr = sB + r * 128 + ((u ^ (r & 7)) << 4);
                asm volatile("ldmatrix.sync.aligned.m8n8.x4.shared.b16 {%0,%1,%2,%3}, [%4];"
                    : "=r"(b[jj*2][0]), "=r"(b[jj*2][1]), "=r"(b[jj*2+1][0]), "=r"(b[jj*2+1][1])
                    : "r"(addr));
            }
            #pragma unroll
            for (int i = 0; i < 2; i++)
                #pragma unroll
                for (int j = 0; j < BJ; j++)
                    asm volatile(
                        "mma.sync.aligned.m16n8k16.row.col.f32.bf16.bf16.f32 "
                        "{%0,%1,%2,%3}, {%4,%5,%6,%7}, {%8,%9}, {%0,%1,%2,%3};"
                        : "+f"(acc[i][j][0]), "+f"(acc[i][j][1]),
                          "+f"(acc[i][j][2]), "+f"(acc[i][j][3])
                        : "r"(a[i][0]), "r"(a[i][1]), "r"(a[i][2]), "r"(a[i][3]),
                          "r"(b[j][0]), "r"(b[j][1]));
        }
        __syncthreads();
    }

    // ---- epilogue: direct stores with fused bias / softplus / residual ----
    #pragma unroll
    for (int i = 0; i < 2; i++) {
        int r0 = bm + wm * 32 + i * 16 + (lane >> 2);
        #pragma unroll
        for (int j = 0; j < BJ; j++) {
            int n0 = bn + wn * WTN + j * 8 + 2 * (lane & 3);
            #pragma unroll
            for (int h = 0; h < 2; h++) {
                int r = r0 + h * 8;
                float v0 = acc[i][j][h * 2 + 0];
                float v1 = acc[i][j][h * 2 + 1];
                if (bias) { v0 += bias[n0]; v1 += bias[n0 + 1]; }
                if (act) {
                    v0 = (v0 > 20.f) ? v0 : log1pf(expf(v0));
                    v1 = (v1 > 20.f) ? v1 : log1pf(expf(v1));
                }
                if (resid) {
                    v0 += resid[(size_t)r * ldr + n0];
                    v1 += resid[(size_t)r * ldr + n0 + 1];
                }
                if (n0 + 1 < Nact) {
                    *(float2*)(C + (size_t)r * ldc + n0) = make_float2(v0, v1);
                } else if (n0 < Nact) {
                    C[(size_t)r * ldc + n0] = v0;
                }
            }
        }
    }
}

// ---------------- LayerNorm -> split-bf16 extended A ----------------
__global__ __launch_bounds__(256) void ln_kernel(const float* __restrict__ x,
                                                 const float* __restrict__ g,
                                                 const float* __restrict__ b) {
    int row = blockIdx.x;
    const float* xr = x + (size_t)row * DIMc;
    float sum = 0.f, sq = 0.f;
    for (int i = threadIdx.x; i < DIMc; i += 256) {
        float v = xr[i];
        sum += v; sq += v * v;
    }
    #pragma unroll
    for (int o = 16; o; o >>= 1) {
        sum += __shfl_xor_sync(0xffffffffu, sum, o);
        sq  += __shfl_xor_sync(0xffffffffu, sq, o);
    }
    __shared__ float s1[8], s2[8], red[2];
    int w = threadIdx.x >> 5, l = threadIdx.x & 31;
    if (l == 0) { s1[w] = sum; s2[w] = sq; }
    __syncthreads();
    if (threadIdx.x == 0) {
        float a = 0.f, c = 0.f;
        #pragma unroll
        for (int i = 0; i < 8; i++) { a += s1[i]; c += s2[i]; }
        float mu = a / DIMc;
        red[0] = mu;
        red[1] = c / DIMc - mu * mu;
    }
    __syncthreads();
    float mu = red[0];
    float inv = rsqrtf(red[1] + 1e-5f);
    __nv_bfloat16* out = g_xnE + (size_t)row * 2 * DIMc;
    for (int i = threadIdx.x; i < DIMc; i += 256) {
        float v = (xr[i] - mu) * inv * g[i] + b[i];
        __nv_bfloat16 h, lo;
        split_bf16(v, h, lo);
        out[i] = h;
        out[DIMc + i] = lo;
    }
}

// ---------------- weight -> split-bf16 ext (with row padding) ----------------
__global__ __launch_bounds__(256) void wext_kernel(const float* __restrict__ W,
                                                   __nv_bfloat16* __restrict__ out,
                                                   int Rin, int K, int total) {
    int idx = blockIdx.x * 256 + threadIdx.x;
    if (idx >= total) return;
    int r = idx / K, k = idx - r * K;
    float v = (r < Rin) ? W[(size_t)r * K + k] : 0.f;
    __nv_bfloat16 h, lo;
    split_bf16(v, h, lo);
    out[(size_t)r * 2 * K + k]     = h;
    out[(size_t)r * 2 * K + K + k] = lo;
}

// ---------------- depthwise causal conv (k=4) + SiLU ----------------
__global__ __launch_bounds__(256) void conv_silu_kernel(const float* __restrict__ convw,
                                                        const float* __restrict__ convb) {
    int idx = blockIdx.x * 256 + threadIdx.x;
    if (idx >= MROWS * DINNER) return;
    int d = idx & (DINNER - 1);
    int m = idx >> 11;
    int l = m & (Lc - 1);
    float acc = convb[d];
    #pragma unroll
    for (int k = 0; k < DCONV; k++) {
        int ll = l - (DCONV - 1) + k;
        if (ll >= 0)
            acc = fmaf(g_xz[(size_t)(m - (DCONV - 1) + k) * (2 * DINNER) + d],
                       convw[d * DCONV + k], acc);
    }
    acc = acc / (1.f + expf(-acc));
    g_ucF[idx] = acc;
    __nv_bfloat16 h, lo;
    split_bf16(acc, h, lo);
    g_ucE[(size_t)m * 2 * DINNER + d]          = h;
    g_ucE[(size_t)m * 2 * DINNER + DINNER + d] = lo;
}

// ---------------- dt_r slice -> split-bf16 ext ----------------
__global__ __launch_bounds__(256) void dtr_kernel() {
    int idx = blockIdx.x * 256 + threadIdx.x;
    if (idx >= MROWS * DTRANK) return;
    int m = idx >> 6, k = idx & 63;
    float v = g_xdbl[(size_t)m * XDBL_N + k];
    __nv_bfloat16 h, lo;
    split_bf16(v, h, lo);
    g_dtrE[(size_t)m * 2 * DTRANK + k]          = h;
    g_dtrE[(size_t)m * 2 * DTRANK + DTRANK + k] = lo;
}

// ---------------- selective scan + gate -> split-bf16 y ----------------
__global__ __launch_bounds__(256) void scan_kernel(const float* __restrict__ A_log,
                                                   const float* __restrict__ Dp) {
    int t = blockIdx.x * 256 + threadIdx.x;
    int n = t & 15;
    int d = (t >> 4) & (DINNER - 1);
    int b = t >> 15;
    float A  = -expf(A_log[d * DSTATE + n]);
    float Dd = Dp[d];
    float h  = 0.f;
    size_t base = (size_t)b * Lc;
    for (int l = 0; l < Lc; l++) {
        size_t m = base + l;
        float dt = g_dt[m * DINNER + d];
        float u  = g_ucF[m * DINNER + d];
        float Bn = g_xdbl[m * XDBL_N + DTRANK + n];
        float Cn = g_xdbl[m * XDBL_N + DTRANK + DSTATE + n];
        float dA = expf(dt * A);
        h = fmaf(dA, h, dt * u * Bn);
        float p = h * Cn;
        p += __shfl_xor_sync(0xffffffffu, p, 8);
        p += __shfl_xor_sync(0xffffffffu, p, 4);
        p += __shfl_xor_sync(0xffffffffu, p, 2);
        p += __shfl_xor_sync(0xffffffffu, p, 1);
        if (n == 0) {
            float z = g_xz[m * (2 * DINNER) + DINNER + d];
            float y = (p + u * Dd) * (z / (1.f + expf(-z)));
            __nv_bfloat16 hh, lo;
            split_bf16(y, hh, lo);
            g_yE[m * 2 * DINNER + d]          = hh;
            g_yE[m * 2 * DINNER + DINNER + d] = lo;
        }
    }
}

// ---------------- launch ----------------
extern "C" void kernel_launch(void* const* d_in, const int* in_sizes, int n_in,
                              void* d_out, int out_size) {
    const float* x      = (const float*)d_in[0];
    const float* ln_g   = (const float*)d_in[1];
    const float* ln_b   = (const float*)d_in[2];
    const float* W_in   = (const float*)d_in[3];
    const float* conv_w = (const float*)d_in[4];
    const float* conv_b = (const float*)d_in[5];
    const float* W_x    = (const float*)d_in[6];
    const float* W_dt   = (const float*)d_in[7];
    const float* b_dt   = (const float*)d_in[8];
    const float* A_log  = (const float*)d_in[9];
    const float* Dvec   = (const float*)d_in[10];
    const float* W_out  = (const float*)d_in[11];
    float* out = (float*)d_out;

    __nv_bfloat16 *xnE, *WinE, *ucE, *WxE, *dtrE, *WdtE, *yE, *WoutE;
    float *xz, *xdbl, *dt;
    cudaGetSymbolAddress((void**)&xnE,   g_xnE);
    cudaGetSymbolAddress((void**)&WinE,  g_WinE);
    cudaGetSymbolAddress((void**)&xz,    g_xz);
    cudaGetSymbolAddress((void**)&ucE,   g_ucE);
    cudaGetSymbolAddress((void**)&WxE,   g_WxE);
    cudaGetSymbolAddress((void**)&xdbl,  g_xdbl);
    cudaGetSymbolAddress((void**)&dtrE,  g_dtrE);
    cudaGetSymbolAddress((void**)&WdtE,  g_WdtE);
    cudaGetSymbolAddress((void**)&dt,    g_dt);
    cudaGetSymbolAddress((void**)&yE,    g_yE);
    cudaGetSymbolAddress((void**)&WoutE, g_WoutE);

    static int smem_set = 0;
    if (!smem_set) {
        cudaFuncSetAttribute(gemm_mma<128>, cudaFuncAttributeMaxDynamicSharedMemorySize, 3 * (128 * 128 + 128 * 128));
        cudaFuncSetAttribute(gemm_mma<64>,  cudaFuncAttributeMaxDynamicSharedMemorySize, 3 * (64 * 128 + 128 * 128));
        smem_set = 1;
    }
    const int SM128 = 3 * (128 * 128 + 128 * 128);   // 98304
    const int SM64  = 3 * (64 * 128 + 128 * 128);    // 73728

    // weight conversions + LN
    wext_kernel<<<(4096 * DIMc + 255) / 256, 256>>>(W_in, WinE, 4096, DIMc, 4096 * DIMc);
    wext_kernel<<<(128 * DINNER + 255) / 256, 256>>>(W_x, WxE, XDBL_N, DINNER, 128 * DINNER);
    wext_kernel<<<(DINNER * DTRANK + 255) / 256, 256>>>(W_dt, WdtE, DINNER, DTRANK, DINNER * DTRANK);
    wext_kernel<<<(DIMc * DINNER + 255) / 256, 256>>>(W_out, WoutE, DIMc, DINNER, DIMc * DINNER);
    ln_kernel<<<MROWS, 256>>>(x, ln_g, ln_b);

    // GEMM1: xz = xn @ W_in^T   (8192 x 4096, K=1024)
    gemm_mma<128><<<dim3(4096 / 128, MROWS / 128), 256, SM128>>>(
        xnE, WinE, xz, 2 * DINNER, 2 * DINNER, DIMc, nullptr, nullptr, 0, 0);

    // conv + SiLU
    conv_silu_kernel<<<(MROWS * DINNER) / 256, 256>>>(conv_w, conv_b);

    // GEMM2: x_dbl = uc @ W_x^T  (8192 x 96 -> pad 128, K=2048), BM=64 for occupancy
    gemm_mma<64><<<dim3(1, MROWS / 64), 256, SM64>>>(
        ucE, WxE, xdbl, XDBL_N, XDBL_N, DINNER, nullptr, nullptr, 0, 0);

    // dt_r extraction
    dtr_kernel<<<(MROWS * DTRANK) / 256, 256>>>();

    // GEMM3: dt = softplus(dt_r @ W_dt^T + b_dt)  (8192 x 2048, K=64)
    gemm_mma<128><<<dim3(DINNER / 128, MROWS / 128), 256, SM128>>>(
        dtrE, WdtE, dt, DINNER, DINNER, DTRANK, b_dt, nullptr, 0, 1);

    // scan + gating -> yE
    scan_kernel<<<(Bc * DINNER * DSTATE) / 256, 256>>>(A_log, Dvec);

    // GEMM4: out = x + y @ W_out^T  (8192 x 1024, K=2048)
    gemm_mma<128><<<dim3(DIMc / 128, MROWS / 128), 256, SM128>>>(
        yE, WoutE, out, DIMc, DIMc, DINNER, nullptr, x, DIMc, 0);
}